// round 5
// baseline (speedup 1.0000x reference)
#include <cuda_runtime.h>
#include <math.h>

#define Bsz 128
#define Tsz 256
#define Isz 512
#define Hsz 1024
#define Mpre (Bsz*Tsz)

#define BM 128
#define BN 64
#define BK 16

// ---------------- scratch (static device allocations; no cudaMalloc) --------
__device__ float g_P[5][Tsz][Bsz][Hsz];      // gate preactivations, [g][t][b][h]
__device__ float g_HS[(size_t)Mpre*Hsz];     // all hidden states, (b*T+t, h)
__device__ float g_h[2][Bsz*Hsz];            // ping-pong hidden
__device__ float g_c[Bsz*Hsz];               // cell state
__device__ int   g_flag[Bsz*8];              // producer flags, 32B padded

// ---------------- helpers ---------------------------------------------------
__device__ __forceinline__ float to_tf32(float x){
    float r; asm("cvt.rna.tf32.f32 %0, %1;" : "=f"(r) : "f"(x)); return r;
}
__device__ __forceinline__ void mma8(float c[4], const float a[4], const float b[2]){
    asm volatile("mma.sync.aligned.m16n8k8.row.col.f32.tf32.tf32.f32 "
        "{%0,%1,%2,%3},{%4,%5,%6,%7},{%8,%9},{%0,%1,%2,%3};"
        : "+f"(c[0]),"+f"(c[1]),"+f"(c[2]),"+f"(c[3])
        : "r"(__float_as_uint(a[0])),"r"(__float_as_uint(a[1])),
          "r"(__float_as_uint(a[2])),"r"(__float_as_uint(a[3])),
          "r"(__float_as_uint(b[0])),"r"(__float_as_uint(b[1])));
}
__device__ __forceinline__ float sig_(float x){ return 1.f/(1.f+expf(-x)); }
__device__ __forceinline__ int ld_acq(const int* p){
    int v; asm volatile("ld.global.acquire.gpu.b32 %0, [%1];" : "=r"(v) : "l"(p) : "memory");
    return v;
}
__device__ __forceinline__ float4 ldcg4(const float* p){
    return __ldcg(reinterpret_cast<const float4*>(p));
}

// ---------------- shared GEMM panel: C(128x64) += A(m0..,K) * W(n0..,K)^T ---
__device__ __forceinline__ void gemm_panel(
    const float* __restrict__ A, int lda,
    const float* __restrict__ W, int ldw,
    int K, int m0, int n0, int tid,
    float (&cacc)[2][4][4],
    float (&As)[BM][BK+1], float (&Bs)[BN][BK+1])
{
    const int lane = tid & 31, wid = tid >> 5;
    const int wm = wid & 3, wn = wid >> 2;
    const int gid = lane >> 2, tig = lane & 3;

    for (int k0 = 0; k0 < K; k0 += BK) {
        for (int i = tid; i < BM*(BK/4); i += 256) {
            int r = i >> 2, c4 = (i & 3) * 4;
            float4 v = *reinterpret_cast<const float4*>(A + (size_t)(m0+r)*lda + k0 + c4);
            As[r][c4+0]=to_tf32(v.x); As[r][c4+1]=to_tf32(v.y);
            As[r][c4+2]=to_tf32(v.z); As[r][c4+3]=to_tf32(v.w);
        }
        for (int i = tid; i < BN*(BK/4); i += 256) {
            int r = i >> 2, c4 = (i & 3) * 4;
            float4 v = *reinterpret_cast<const float4*>(W + (size_t)(n0+r)*ldw + k0 + c4);
            Bs[r][c4+0]=to_tf32(v.x); Bs[r][c4+1]=to_tf32(v.y);
            Bs[r][c4+2]=to_tf32(v.z); Bs[r][c4+3]=to_tf32(v.w);
        }
        __syncthreads();
        #pragma unroll
        for (int kk = 0; kk < 2; kk++) {
            float a[2][4], bf2[4][2];
            #pragma unroll
            for (int mt = 0; mt < 2; mt++) {
                int rb = wm*32 + mt*16;
                a[mt][0] = As[rb+gid  ][kk*8+tig  ];
                a[mt][1] = As[rb+gid+8][kk*8+tig  ];
                a[mt][2] = As[rb+gid  ][kk*8+tig+4];
                a[mt][3] = As[rb+gid+8][kk*8+tig+4];
            }
            #pragma unroll
            for (int nt = 0; nt < 4; nt++) {
                int nb = wn*32 + nt*8;
                bf2[nt][0] = Bs[nb+gid][kk*8+tig  ];
                bf2[nt][1] = Bs[nb+gid][kk*8+tig+4];
            }
            #pragma unroll
            for (int mt = 0; mt < 2; mt++)
                #pragma unroll
                for (int nt = 0; nt < 4; nt++)
                    mma8(cacc[mt][nt], a[mt], bf2[nt]);
        }
        __syncthreads();
    }
}

// ---------------- phase A: P_g = X_g @ W_g^T + b_g --------------------------
__global__ __launch_bounds__(256)
void gemm_pre(const float* __restrict__ x, const float* __restrict__ xd,
              const float* __restrict__ W0, const float* __restrict__ W1,
              const float* __restrict__ W2, const float* __restrict__ W3,
              const float* __restrict__ W4,
              const float* __restrict__ b0, const float* __restrict__ b1,
              const float* __restrict__ b2, const float* __restrict__ b3,
              const float* __restrict__ b4)
{
    __shared__ float As[BM][BK+1];
    __shared__ float Bs[BN][BK+1];
    const int gate = blockIdx.z;
    const float* A    = (gate == 4) ? xd : x;
    const float* W    = gate==0?W0 : gate==1?W1 : gate==2?W2 : gate==3?W3 : W4;
    const float* bias = gate==0?b0 : gate==1?b1 : gate==2?b2 : gate==3?b3 : b4;
    const int m0 = blockIdx.y * BM;
    const int n0 = blockIdx.x * BN;
    const int tid = threadIdx.x;

    float cacc[2][4][4];
    #pragma unroll
    for (int i=0;i<2;i++) for (int j=0;j<4;j++) for (int k=0;k<4;k++) cacc[i][j][k]=0.f;

    gemm_panel(A, Isz, W, Isz, Isz, m0, n0, tid, cacc, As, Bs);

    const int lane = tid & 31, wid = tid >> 5;
    const int wm = wid & 3, wn = wid >> 2;
    const int gid = lane >> 2, tig = lane & 3;
    #pragma unroll
    for (int mt=0; mt<2; mt++)
        #pragma unroll
        for (int nt=0; nt<4; nt++) {
            int row = m0 + wm*32 + mt*16 + gid;
            int b = row >> 8;
            int tt = row & 255;
            int col = n0 + wn*32 + nt*8 + 2*tig;
            float bv0 = bias[col], bv1 = bias[col+1];
            g_P[gate][tt  ][b][col  ] = cacc[mt][nt][0] + bv0;
            g_P[gate][tt  ][b][col+1] = cacc[mt][nt][1] + bv1;
            g_P[gate][tt+8][b][col  ] = cacc[mt][nt][2] + bv0;
            g_P[gate][tt+8][b][col+1] = cacc[mt][nt][3] + bv1;
        }
}

// ---------------- phase B: persistent recurrence kernel ---------------------
// 128 CTAs x 512 threads. 16 warps = 4 m-tiles x 4 k-quarters.
// Weights SMEM-resident (pair-permuted + XOR-swizzled). H tiles pair-permuted.
// k-within-8 permutation: k -> (k&3)*2 + (k>>2)  => frag pairs {k,k+4} adjacent.
#define SBK 32
#define HSTR 36
#define W_OFF 0                         /* 40*1024 floats               */
#define HS_OFF 40960                    /* 2 x 128*36 floats            */
#define RED_OFF (40960 + 9216)          /* 4*32*41 floats               */
#define SMEM_FLOATS (50176 + 5248)      /* 55424 floats = 221,696 B     */

__global__ void __launch_bounds__(512, 1)
lstm_persist(const float* __restrict__ Whi, const float* __restrict__ Whf,
             const float* __restrict__ Whg, const float* __restrict__ Who,
             const float* __restrict__ Whd)
{
    extern __shared__ float sm[];
    const int cb  = blockIdx.x;
    const int h0  = cb * 8;
    const int tid = threadIdx.x, lane = tid & 31, wid = tid >> 5;
    const int gid = lane >> 2, tig = lane & 3;
    const int wm  = wid & 3;          // m-tile (32 batch rows)
    const int kq  = wid >> 2;         // k-quarter (8 cols of each 32-tile)

    // ---- load weights into SMEM once (tf32, pair-permuted, XOR-swizzled) ----
    for (int i = tid; i < 40*1024; i += 512) {
        int row = i >> 10, k = i & 1023;
        int g = row >> 3, r = row & 7;
        const float* Wg = g==0?Whi : g==1?Whf : g==2?Whg : g==3?Who : Whd;
        float v = Wg[(size_t)(h0+r)*Hsz + k];
        int kp = (k & ~7) | (((k & 3) << 1) | ((k >> 2) & 1));
        sm[W_OFF + row*1024 + (kp ^ ((row & 7) * 4))] = to_tf32(v);
    }
    __syncthreads();

    const int ar = tid >> 2;            // h-tile row 0..127
    const int g8 = (tid & 3) * 8;       // 8-col group within 32-wide tile

    for (int t = 0; t < Tsz; t++) {
        const float* __restrict__ hprev = g_h[t & 1];

        // wait producer group 0
        if (wid == 0) {
            const int* fp = &g_flag[lane * 8];
            while (ld_acq(fp) < t) {}
        }
        __syncthreads();

        // prologue: tile 0 -> buf 0 (pair-permuted)
        {
            float4 v0 = ldcg4(hprev + (size_t)ar*Hsz + g8);
            float4 v1 = ldcg4(hprev + (size_t)ar*Hsz + g8 + 4);
            float* p = &sm[HS_OFF + ar*HSTR + g8];
            *reinterpret_cast<float4*>(p)   = make_float4(to_tf32(v0.x),to_tf32(v1.x),to_tf32(v0.y),to_tf32(v1.y));
            *reinterpret_cast<float4*>(p+4) = make_float4(to_tf32(v0.z),to_tf32(v1.z),to_tf32(v0.w),to_tf32(v1.w));
        }
        __syncthreads();

        float cacc[2][5][4];
        #pragma unroll
        for (int mt=0; mt<2; mt++)
            #pragma unroll
            for (int g=0; g<5; g++)
                { cacc[mt][g][0]=0.f; cacc[mt][g][1]=0.f; cacc[mt][g][2]=0.f; cacc[mt][g][3]=0.f; }

        float4 r0, r1;
        for (int k0 = 0; k0 < Hsz/SBK; k0++) {
            const int buf = k0 & 1;
            const bool more = (k0 < Hsz/SBK - 1);
            if (more) {
                if (((k0+1) & 7) == 0) {
                    if (wid == 0) {
                        const int* fp = &g_flag[(((k0+1) >> 3)*32 + lane) * 8];
                        while (ld_acq(fp) < t) {}
                    }
                    __syncthreads();
                }
                const int kn = (k0+1)*SBK + g8;
                r0 = ldcg4(hprev + (size_t)ar*Hsz + kn);
                r1 = ldcg4(hprev + (size_t)ar*Hsz + kn + 4);
            }

            // ---- compute: 1 kk-slice per warp (k-quarter) ----
            {
                const float* HS_ = &sm[HS_OFF + buf*4608];
                const int kb  = k0*32 + kq*8;       // weight col base
                const int kbl = kq*8;               // h-tile col base
                float a[2][4];
                #pragma unroll
                for (int mt=0; mt<2; mt++) {
                    const float* hp = HS_ + (wm*32 + mt*16 + gid)*HSTR + kbl + 2*tig;
                    float2 p0 = *reinterpret_cast<const float2*>(hp);
                    float2 p1 = *reinterpret_cast<const float2*>(hp + 8*HSTR);
                    a[mt][0]=p0.x; a[mt][1]=p1.x; a[mt][2]=p0.y; a[mt][3]=p1.y;
                }
                const int wofs = (kb + 2*tig) ^ (gid * 4);
                #pragma unroll
                for (int g=0; g<5; g++) {
                    float2 bb = *reinterpret_cast<const float2*>(
                        &sm[W_OFF + (g*8 + gid)*1024 + wofs]);
                    float br[2] = { bb.x, bb.y };
                    mma8(cacc[0][g], a[0], br);
                    mma8(cacc[1][g], a[1], br);
                }
            }

            if (more) {
                float* p = &sm[HS_OFF + (buf^1)*4608 + ar*HSTR + g8];
                *reinterpret_cast<float4*>(p)   = make_float4(to_tf32(r0.x),to_tf32(r1.x),to_tf32(r0.y),to_tf32(r1.y));
                *reinterpret_cast<float4*>(p+4) = make_float4(to_tf32(r0.z),to_tf32(r1.z),to_tf32(r0.w),to_tf32(r1.w));
            }
            __syncthreads();
        }

        // ---- prefetch epilogue operands (hides DRAM under reduction) ----
        float pre[2][4][5], cpre[2][4];
        if (kq == 0) {
            #pragma unroll
            for (int mt=0; mt<2; mt++)
                #pragma unroll
                for (int r=0; r<4; r++) {
                    int b = wm*32 + mt*16 + gid + ((r >> 1) ? 8 : 0);
                    int h = h0 + 2*tig + (r & 1);
                    size_t pofs = ((size_t)t*Bsz + b)*Hsz + h;
                    #pragma unroll
                    for (int g=0; g<5; g++)
                        pre[mt][r][g] = g_P[g][0][0][pofs];
                    cpre[mt][r] = g_c[b*Hsz + h];
                }
        }

        // ---- 3-round tree reduction over k-quarters ----
        float* red = &sm[RED_OFF + wm*(32*41) + lane*41];
        if (kq == 1) {
            #pragma unroll
            for (int mt=0; mt<2; mt++) for (int g=0; g<5; g++) for (int r=0; r<4; r++)
                red[mt*20 + g*4 + r] = cacc[mt][g][r];
        }
        __syncthreads();
        if (kq == 0) {
            #pragma unroll
            for (int mt=0; mt<2; mt++) for (int g=0; g<5; g++) for (int r=0; r<4; r++)
                cacc[mt][g][r] += red[mt*20 + g*4 + r];
        }
        __syncthreads();
        if (kq == 3) {
            #pragma unroll
            for (int mt=0; mt<2; mt++) for (int g=0; g<5; g++) for (int r=0; r<4; r++)
                red[mt*20 + g*4 + r] = cacc[mt][g][r];
        }
        __syncthreads();
        if (kq == 2) {
            #pragma unroll
            for (int mt=0; mt<2; mt++) for (int g=0; g<5; g++) for (int r=0; r<4; r++)
                cacc[mt][g][r] += red[mt*20 + g*4 + r];
        }
        __syncthreads();
        if (kq == 2) {
            #pragma unroll
            for (int mt=0; mt<2; mt++) for (int g=0; g<5; g++) for (int r=0; r<4; r++)
                red[mt*20 + g*4 + r] = cacc[mt][g][r];
        }
        __syncthreads();

        if (kq == 0) {
            float* __restrict__ hnext = g_h[(t+1) & 1];
            #pragma unroll
            for (int mt=0; mt<2; mt++)
                #pragma unroll
                for (int r=0; r<4; r++) {
                    int b = wm*32 + mt*16 + gid + ((r >> 1) ? 8 : 0);
                    int h = h0 + 2*tig + (r & 1);
                    float s = red[mt*20 + 0*4 + r];  // dummy init to keep indices clear
                    (void)s;
                    float pi = cacc[mt][0][r] + red[mt*20 + 0*4 + r] + pre[mt][r][0];
                    float pf = cacc[mt][1][r] + red[mt*20 + 1*4 + r] + pre[mt][r][1];
                    float pg = cacc[mt][2][r] + red[mt*20 + 2*4 + r] + pre[mt][r][2];
                    float po = cacc[mt][3][r] + red[mt*20 + 3*4 + r] + pre[mt][r][3];
                    float pd = cacc[mt][4][r] + red[mt*20 + 4*4 + r] + pre[mt][r][4];
                    float iv = sig_(pi), fv = sig_(pf), gv = tanhf(pg);
                    float ov = sig_(po), dv = sig_(pd);
                    float cp = cpre[mt][r];
                    float cn = fv*cp + iv*gv + dv;
                    float hn = ov * tanhf(cn);
                    g_c[b*Hsz + h] = cn;
                    hnext[b*Hsz + h] = hn;
                    g_HS[((size_t)b*Tsz + t)*Hsz + h] = hn;
                }
        }
        __syncthreads();

        if (tid == 0) {
            __threadfence();
            atomicExch(&g_flag[cb*8], t + 1);
        }
    }
}

// ---------------- phase C: y = tanh(X@Wro^T + HS@Who^T + Wrb) ---------------
__global__ __launch_bounds__(256)
void gemm_out(const float* __restrict__ x, const float* __restrict__ Wro,
              const float* __restrict__ Who, const float* __restrict__ Wrb,
              float* __restrict__ y)
{
    __shared__ float As[BM][BK+1];
    __shared__ float Bs[BN][BK+1];
    const int m0 = blockIdx.y * BM;
    const int n0 = blockIdx.x * BN;
    const int tid = threadIdx.x;

    float cacc[2][4][4];
    #pragma unroll
    for (int i=0;i<2;i++) for (int j=0;j<4;j++) for (int k=0;k<4;k++) cacc[i][j][k]=0.f;

    gemm_panel(x,        Isz, Wro, Isz, Isz, m0, n0, tid, cacc, As, Bs);
    gemm_panel(&g_HS[0], Hsz, Who, Hsz, Hsz, m0, n0, tid, cacc, As, Bs);

    const int lane = tid & 31, wid = tid >> 5;
    const int wm = wid & 3, wn = wid >> 2;
    const int gid = lane >> 2, tig = lane & 3;
    #pragma unroll
    for (int mt=0; mt<2; mt++)
        #pragma unroll
        for (int nt=0; nt<4; nt++) {
            int row = m0 + wm*32 + mt*16 + gid;
            int col = n0 + wn*32 + nt*8 + 2*tig;
            float bv0 = Wrb[col], bv1 = Wrb[col+1];
            y[(size_t)row*Hsz + col  ]     = tanhf(cacc[mt][nt][0] + bv0);
            y[(size_t)row*Hsz + col+1]     = tanhf(cacc[mt][nt][1] + bv1);
            y[(size_t)(row+8)*Hsz + col  ] = tanhf(cacc[mt][nt][2] + bv0);
            y[(size_t)(row+8)*Hsz + col+1] = tanhf(cacc[mt][nt][3] + bv1);
        }
}

// ---------------- small state init / tail copy ------------------------------
__global__ void init_state(const float* __restrict__ hidden, const float* __restrict__ cell){
    int i = blockIdx.x * 256 + threadIdx.x;
    g_h[0][i] = hidden[i];
    g_c[i]    = cell[i];
    if (blockIdx.x == 0 && threadIdx.x < Bsz) g_flag[threadIdx.x * 8] = 0;
}
__global__ void write_tail(float* __restrict__ out){
    int i = blockIdx.x * 256 + threadIdx.x;
    out[(size_t)Bsz*Tsz*Hsz + i]              = g_h[0][i];
    out[(size_t)Bsz*Tsz*Hsz + Bsz*Hsz + i]    = g_c[i];
}

// ---------------- launcher ---------------------------------------------------
extern "C" void kernel_launch(void* const* d_in, const int* in_sizes, int n_in,
                              void* d_out, int out_size)
{
    const float *x, *xd, *hidden, *cell;
    const float *Wii,*Wif,*Wig,*Wio,*Wid,*Wro,*Whi,*Whf,*Whg,*Who,*Whd;
    const float *bi,*bf,*bg,*bo,*bd,*Wrb;

    x      = (const float*)d_in[0];
    xd     = (const float*)d_in[1];
    hidden = (const float*)d_in[2];
    cell   = (const float*)d_in[3];

    if (in_sizes[5] == Hsz*Isz) {
        Wii=(const float*)d_in[4];  Wif=(const float*)d_in[5];  Wig=(const float*)d_in[6];
        Wio=(const float*)d_in[7];  Wid=(const float*)d_in[8];  Wro=(const float*)d_in[9];
        Whi=(const float*)d_in[10]; Whf=(const float*)d_in[11]; Whg=(const float*)d_in[12];
        Who=(const float*)d_in[13]; Whd=(const float*)d_in[14];
        bi=(const float*)d_in[15];  bf=(const float*)d_in[16];  bg=(const float*)d_in[17];
        bo=(const float*)d_in[18];  bd=(const float*)d_in[19];  Wrb=(const float*)d_in[20];
    } else {
        Wii=(const float*)d_in[4];  Whi=(const float*)d_in[5];  bi =(const float*)d_in[6];
        Wif=(const float*)d_in[7];  Whf=(const float*)d_in[8];  bf =(const float*)d_in[9];
        Wig=(const float*)d_in[10]; Whg=(const float*)d_in[11]; bg =(const float*)d_in[12];
        Wio=(const float*)d_in[13]; Who=(const float*)d_in[14]; bo =(const float*)d_in[15];
        Wid=(const float*)d_in[16]; Whd=(const float*)d_in[17]; bd =(const float*)d_in[18];
        Wro=(const float*)d_in[19]; Wrb=(const float*)d_in[20];
    }

    float* out = (float*)d_out;

    cudaFuncSetAttribute(lstm_persist, cudaFuncAttributeMaxDynamicSharedMemorySize,
                         SMEM_FLOATS * (int)sizeof(float));

    init_state<<<(Bsz*Hsz)/256, 256>>>(hidden, cell);

    dim3 gpre(Hsz/BN, Mpre/BM, 5);
    gemm_pre<<<gpre, 256>>>(x, xd, Wii, Wif, Wig, Wio, Wid, bi, bf, bg, bo, bd);

    lstm_persist<<<Bsz, 512, SMEM_FLOATS * (int)sizeof(float)>>>(Whi, Whf, Whg, Who, Whd);

    gemm_out<<<dim3(Hsz/BN, Mpre/BM), 256>>>(x, Wro, Who, Wrb, out);

    write_tail<<<(Bsz*Hsz)/256, 256>>>(out);
}

// round 7
// speedup vs baseline: 1.1543x; 1.1543x over previous
#include <cuda_runtime.h>
#include <cstdint>
#include <math.h>

#define Bsz 128
#define Tsz 256
#define Isz 512
#define Hsz 1024
#define Mpre (Bsz*Tsz)

#define BM 128
#define BN 64
#define BK 16

// ---------------- scratch (static device allocations; no cudaMalloc) --------
__device__ float g_P[5][Tsz][Bsz][Hsz];      // gate preactivations, [g][t][b][h]
__device__ float g_HS[(size_t)Mpre*Hsz];     // all hidden states, (b*T+t, h)
__device__ float g_h[2][Bsz*Hsz];            // ping-pong hidden
__device__ float g_c[Bsz*Hsz];               // cell state
__device__ int   g_flag[Bsz*8];              // producer flags, 32B padded

// ---------------- helpers ---------------------------------------------------
__device__ __forceinline__ float to_tf32(float x){
    float r; asm("cvt.rna.tf32.f32 %0, %1;" : "=f"(r) : "f"(x)); return r;
}
__device__ __forceinline__ void mma8(float c[4], const float a[4], const float b[2]){
    asm volatile("mma.sync.aligned.m16n8k8.row.col.f32.tf32.tf32.f32 "
        "{%0,%1,%2,%3},{%4,%5,%6,%7},{%8,%9},{%0,%1,%2,%3};"
        : "+f"(c[0]),"+f"(c[1]),"+f"(c[2]),"+f"(c[3])
        : "r"(__float_as_uint(a[0])),"r"(__float_as_uint(a[1])),
          "r"(__float_as_uint(a[2])),"r"(__float_as_uint(a[3])),
          "r"(__float_as_uint(b[0])),"r"(__float_as_uint(b[1])));
}
__device__ __forceinline__ float sig_(float x){
    return __fdividef(1.f, 1.f + __expf(-x));
}
__device__ __forceinline__ float tanh_(float x){
    float e = __expf(2.f * x);
    return 1.f - __fdividef(2.f, e + 1.f);
}
__device__ __forceinline__ int ld_acq(const int* p){
    int v; asm volatile("ld.global.acquire.gpu.b32 %0, [%1];" : "=r"(v) : "l"(p) : "memory");
    return v;
}
__device__ __forceinline__ void cpasync16(unsigned int dst, const float* src){
    asm volatile("cp.async.cg.shared.global [%0], [%1], 16;" :: "r"(dst), "l"(src));
}
#define CP_COMMIT() asm volatile("cp.async.commit_group;" ::: "memory")

// ---------------- shared GEMM panel: C(128x64) += A(m0..,K) * W(n0..,K)^T ---
__device__ __forceinline__ void gemm_panel(
    const float* __restrict__ A, int lda,
    const float* __restrict__ W, int ldw,
    int K, int m0, int n0, int tid,
    float (&cacc)[2][4][4],
    float (&As)[BM][BK+1], float (&Bs)[BN][BK+1])
{
    const int lane = tid & 31, wid = tid >> 5;
    const int wm = wid & 3, wn = wid >> 2;
    const int gid = lane >> 2, tig = lane & 3;

    for (int k0 = 0; k0 < K; k0 += BK) {
        for (int i = tid; i < BM*(BK/4); i += 256) {
            int r = i >> 2, c4 = (i & 3) * 4;
            float4 v = *reinterpret_cast<const float4*>(A + (size_t)(m0+r)*lda + k0 + c4);
            As[r][c4+0]=to_tf32(v.x); As[r][c4+1]=to_tf32(v.y);
            As[r][c4+2]=to_tf32(v.z); As[r][c4+3]=to_tf32(v.w);
        }
        for (int i = tid; i < BN*(BK/4); i += 256) {
            int r = i >> 2, c4 = (i & 3) * 4;
            float4 v = *reinterpret_cast<const float4*>(W + (size_t)(n0+r)*ldw + k0 + c4);
            Bs[r][c4+0]=to_tf32(v.x); Bs[r][c4+1]=to_tf32(v.y);
            Bs[r][c4+2]=to_tf32(v.z); Bs[r][c4+3]=to_tf32(v.w);
        }
        __syncthreads();
        #pragma unroll
        for (int kk = 0; kk < 2; kk++) {
            float a[2][4], bf2[4][2];
            #pragma unroll
            for (int mt = 0; mt < 2; mt++) {
                int rb = wm*32 + mt*16;
                a[mt][0] = As[rb+gid  ][kk*8+tig  ];
                a[mt][1] = As[rb+gid+8][kk*8+tig  ];
                a[mt][2] = As[rb+gid  ][kk*8+tig+4];
                a[mt][3] = As[rb+gid+8][kk*8+tig+4];
            }
            #pragma unroll
            for (int nt = 0; nt < 4; nt++) {
                int nb = wn*32 + nt*8;
                bf2[nt][0] = Bs[nb+gid][kk*8+tig  ];
                bf2[nt][1] = Bs[nb+gid][kk*8+tig+4];
            }
            #pragma unroll
            for (int mt = 0; mt < 2; mt++)
                #pragma unroll
                for (int nt = 0; nt < 4; nt++)
                    mma8(cacc[mt][nt], a[mt], bf2[nt]);
        }
        __syncthreads();
    }
}

// ---------------- phase A: P_g = X_g @ W_g^T + b_g --------------------------
__global__ __launch_bounds__(256)
void gemm_pre(const float* __restrict__ x, const float* __restrict__ xd,
              const float* __restrict__ W0, const float* __restrict__ W1,
              const float* __restrict__ W2, const float* __restrict__ W3,
              const float* __restrict__ W4,
              const float* __restrict__ b0, const float* __restrict__ b1,
              const float* __restrict__ b2, const float* __restrict__ b3,
              const float* __restrict__ b4)
{
    __shared__ float As[BM][BK+1];
    __shared__ float Bs[BN][BK+1];
    const int gate = blockIdx.z;
    const float* A    = (gate == 4) ? xd : x;
    const float* W    = gate==0?W0 : gate==1?W1 : gate==2?W2 : gate==3?W3 : W4;
    const float* bias = gate==0?b0 : gate==1?b1 : gate==2?b2 : gate==3?b3 : b4;
    const int m0 = blockIdx.y * BM;
    const int n0 = blockIdx.x * BN;
    const int tid = threadIdx.x;

    float cacc[2][4][4];
    #pragma unroll
    for (int i=0;i<2;i++) for (int j=0;j<4;j++) for (int k=0;k<4;k++) cacc[i][j][k]=0.f;

    gemm_panel(A, Isz, W, Isz, Isz, m0, n0, tid, cacc, As, Bs);

    const int lane = tid & 31, wid = tid >> 5;
    const int wm = wid & 3, wn = wid >> 2;
    const int gid = lane >> 2, tig = lane & 3;
    #pragma unroll
    for (int mt=0; mt<2; mt++)
        #pragma unroll
        for (int nt=0; nt<4; nt++) {
            int row = m0 + wm*32 + mt*16 + gid;
            int b = row >> 8;
            int tt = row & 255;
            int col = n0 + wn*32 + nt*8 + 2*tig;
            float bv0 = bias[col], bv1 = bias[col+1];
            g_P[gate][tt  ][b][col  ] = cacc[mt][nt][0] + bv0;
            g_P[gate][tt  ][b][col+1] = cacc[mt][nt][1] + bv1;
            g_P[gate][tt+8][b][col  ] = cacc[mt][nt][2] + bv0;
            g_P[gate][tt+8][b][col+1] = cacc[mt][nt][3] + bv1;
        }
}

// ---------------- phase B: persistent recurrence kernel ---------------------
// 128 CTAs x 512 threads (16 warps = 4 m-tiles x 4 k-quarters).
// Weights SMEM-resident, stride 1028 (conflict-free b-frag LDS.32).
// h tiles: cp.async 3-stage pipeline, stride 36 (conflict-free a-frag LDS.32).
#define SBK 32
#define HSTR 36
#define WSTR 1028
#define W_OFF 0                       /* 40*1028 = 41120 floats */
#define HS_OFF 41120                  /* 3 stages x 4608 floats */
#define STAGEF 4608
#define RED_OFF HS_OFF                /* reused after main loop */
#define SMEM_FLOATS (41120 + 3*4608)  /* 54944 floats = 219,776 B */

__global__ void __launch_bounds__(512, 1)
lstm_persist(const float* __restrict__ Whi, const float* __restrict__ Whf,
             const float* __restrict__ Whg, const float* __restrict__ Who,
             const float* __restrict__ Whd)
{
    extern __shared__ float sm[];
    const unsigned int smb = (unsigned int)__cvta_generic_to_shared(sm);
    const int cb  = blockIdx.x;
    const int h0  = cb * 8;
    const int tid = threadIdx.x, lane = tid & 31, wid = tid >> 5;
    const int gid = lane >> 2, tig = lane & 3;
    const int wm  = wid & 3;          // m-tile (32 batch rows)
    const int kq  = wid >> 2;         // k-quarter (8 cols of each 32-tile)

    // ---- load weights into SMEM once (tf32, row-major stride 1028) ----
    for (int i = tid; i < 40*1024; i += 512) {
        int row = i >> 10, k = i & 1023;
        int g = row >> 3, r = row & 7;
        const float* Wg = g==0?Whi : g==1?Whf : g==2?Whg : g==3?Who : Whd;
        sm[W_OFF + row*WSTR + k] = to_tf32(Wg[(size_t)(h0+r)*Hsz + k]);
    }
    __syncthreads();

    // per-thread cp.async coordinates: row = tid>>2, 8-col group = (tid&3)*8
    const int crow = tid >> 2;
    const int cq8  = (tid & 3) * 8;

    for (int t = 0; t < Tsz; t++) {
        const float* __restrict__ hprev = g_h[t & 1];
        const float* hsrc = hprev + (size_t)crow*Hsz + cq8;

        // ---- prologue: poll group 0, then prefetch tiles 0 and 1 ----
        if (wid == 0) {
            const int* fp = &g_flag[lane * 8];
            while (ld_acq(fp) < t) {}
        }
        __syncthreads();
        #pragma unroll
        for (int j = 0; j < 2; j++) {
            unsigned int dst = smb + (HS_OFF + j*STAGEF + crow*HSTR + cq8) * 4;
            cpasync16(dst,      hsrc + j*SBK);
            cpasync16(dst + 16, hsrc + j*SBK + 4);
            CP_COMMIT();
        }

        float cacc[2][5][4];
        #pragma unroll
        for (int mt=0; mt<2; mt++)
            #pragma unroll
            for (int g=0; g<5; g++)
                { cacc[mt][g][0]=0.f; cacc[mt][g][1]=0.f; cacc[mt][g][2]=0.f; cacc[mt][g][3]=0.f; }

        for (int k0 = 0; k0 < Hsz/SBK; k0++) {
            // stage k0 ready when <=1 groups pending
            asm volatile("cp.async.wait_group 1;" ::: "memory");

            const int j = k0 + 2;                 // tile to prefetch this iter
            if (j < Hsz/SBK && (j & 7) == 0) {    // new producer group needed
                if (wid == 0) {
                    const int* fp = &g_flag[((j >> 3)*32 + lane) * 8];
                    while (ld_acq(fp) < t) {}
                }
            }
            __syncthreads();                      // stage visible to all warps

            if (j < Hsz/SBK) {                    // prefetch into stage (j%3)
                unsigned int dst = smb + (HS_OFF + (j%3)*STAGEF + crow*HSTR + cq8) * 4;
                cpasync16(dst,      hsrc + j*SBK);
                cpasync16(dst + 16, hsrc + j*SBK + 4);
            }
            CP_COMMIT();                          // commit every iter (may be empty)

            // ---- compute on stage k0%3 ----
            const float* HS_ = &sm[HS_OFF + (k0%3)*STAGEF];
            float a[2][4];
            #pragma unroll
            for (int mt=0; mt<2; mt++) {
                const float* hp = HS_ + (wm*32 + mt*16 + gid)*HSTR + kq*8 + tig;
                a[mt][0] = to_tf32(hp[0]);
                a[mt][1] = to_tf32(hp[8*HSTR]);
                a[mt][2] = to_tf32(hp[4]);
                a[mt][3] = to_tf32(hp[8*HSTR+4]);
            }
            const int wofs = k0*SBK + kq*8 + tig;
            #pragma unroll
            for (int g=0; g<5; g++) {
                const float* bp = &sm[W_OFF + (g*8 + gid)*WSTR + wofs];
                float br[2] = { bp[0], bp[4] };
                mma8(cacc[0][g], a[0], br);
                mma8(cacc[1][g], a[1], br);
            }
        }
        __syncthreads();   // all compute done before RED overwrites stages

        // ---- prefetch epilogue operands (hide DRAM under reduction) ----
        float pre[2][4][5], cpre[2][4];
        if (kq == 0) {
            #pragma unroll
            for (int mt=0; mt<2; mt++)
                #pragma unroll
                for (int r=0; r<4; r++) {
                    int b = wm*32 + mt*16 + gid + ((r >> 1) ? 8 : 0);
                    int h = h0 + 2*tig + (r & 1);
                    size_t pofs = ((size_t)t*Bsz + b)*Hsz + h;
                    #pragma unroll
                    for (int g=0; g<5; g++)
                        pre[mt][r][g] = g_P[g][0][0][pofs];
                    cpre[mt][r] = g_c[b*Hsz + h];
                }
        }

        // ---- 3-round tree reduction over k-quarters ----
        float* red = &sm[RED_OFF + wm*(32*41) + lane*41];
        if (kq == 1) {
            #pragma unroll
            for (int mt=0; mt<2; mt++) for (int g=0; g<5; g++) for (int r=0; r<4; r++)
                red[mt*20 + g*4 + r] = cacc[mt][g][r];
        }
        __syncthreads();
        if (kq == 0) {
            #pragma unroll
            for (int mt=0; mt<2; mt++) for (int g=0; g<5; g++) for (int r=0; r<4; r++)
                cacc[mt][g][r] += red[mt*20 + g*4 + r];
        }
        __syncthreads();
        if (kq == 3) {
            #pragma unroll
            for (int mt=0; mt<2; mt++) for (int g=0; g<5; g++) for (int r=0; r<4; r++)
                red[mt*20 + g*4 + r] = cacc[mt][g][r];
        }
        __syncthreads();
        if (kq == 2) {
            #pragma unroll
            for (int mt=0; mt<2; mt++) for (int g=0; g<5; g++) for (int r=0; r<4; r++)
                cacc[mt][g][r] += red[mt*20 + g*4 + r];
        }
        __syncthreads();
        if (kq == 2) {
            #pragma unroll
            for (int mt=0; mt<2; mt++) for (int g=0; g<5; g++) for (int r=0; r<4; r++)
                red[mt*20 + g*4 + r] = cacc[mt][g][r];
        }
        __syncthreads();

        if (kq == 0) {
            float* __restrict__ hnext = g_h[(t+1) & 1];
            #pragma unroll
            for (int mt=0; mt<2; mt++)
                #pragma unroll
                for (int r=0; r<4; r++) {
                    int b = wm*32 + mt*16 + gid + ((r >> 1) ? 8 : 0);
                    int h = h0 + 2*tig + (r & 1);
                    float pi = cacc[mt][0][r] + red[mt*20 + 0*4 + r] + pre[mt][r][0];
                    float pf = cacc[mt][1][r] + red[mt*20 + 1*4 + r] + pre[mt][r][1];
                    float pg = cacc[mt][2][r] + red[mt*20 + 2*4 + r] + pre[mt][r][2];
                    float po = cacc[mt][3][r] + red[mt*20 + 3*4 + r] + pre[mt][r][3];
                    float pd = cacc[mt][4][r] + red[mt*20 + 4*4 + r] + pre[mt][r][4];
                    float iv = sig_(pi), fv = sig_(pf), gv = tanh_(pg);
                    float ov = sig_(po), dv = sig_(pd);
                    float cp = cpre[mt][r];
                    float cn = fv*cp + iv*gv + dv;
                    float hn = ov * tanh_(cn);
                    g_c[b*Hsz + h] = cn;
                    hnext[b*Hsz + h] = hn;
                    g_HS[((size_t)b*Tsz + t)*Hsz + h] = hn;
                }
        }
        __syncthreads();

        if (tid == 0) {
            __threadfence();
            atomicExch(&g_flag[cb*8], t + 1);
        }
    }
}

// ---------------- phase C: y = tanh(X@Wro^T + HS@Who^T + Wrb) ---------------
__global__ __launch_bounds__(256)
void gemm_out(const float* __restrict__ x, const float* __restrict__ Wro,
              const float* __restrict__ Who, const float* __restrict__ Wrb,
              float* __restrict__ y)
{
    __shared__ float As[BM][BK+1];
    __shared__ float Bs[BN][BK+1];
    const int m0 = blockIdx.y * BM;
    const int n0 = blockIdx.x * BN;
    const int tid = threadIdx.x;

    float cacc[2][4][4];
    #pragma unroll
    for (int i=0;i<2;i++) for (int j=0;j<4;j++) for (int k=0;k<4;k++) cacc[i][j][k]=0.f;

    gemm_panel(x,        Isz, Wro, Isz, Isz, m0, n0, tid, cacc, As, Bs);
    gemm_panel(&g_HS[0], Hsz, Who, Hsz, Hsz, m0, n0, tid, cacc, As, Bs);

    const int lane = tid & 31, wid = tid >> 5;
    const int wm = wid & 3, wn = wid >> 2;
    const int gid = lane >> 2, tig = lane & 3;
    #pragma unroll
    for (int mt=0; mt<2; mt++)
        #pragma unroll
        for (int nt=0; nt<4; nt++) {
            int row = m0 + wm*32 + mt*16 + gid;
            int col = n0 + wn*32 + nt*8 + 2*tig;
            float bv0 = Wrb[col], bv1 = Wrb[col+1];
            y[(size_t)row*Hsz + col  ]     = tanhf(cacc[mt][nt][0] + bv0);
            y[(size_t)row*Hsz + col+1]     = tanhf(cacc[mt][nt][1] + bv1);
            y[(size_t)(row+8)*Hsz + col  ] = tanhf(cacc[mt][nt][2] + bv0);
            y[(size_t)(row+8)*Hsz + col+1] = tanhf(cacc[mt][nt][3] + bv1);
        }
}

// ---------------- small state init / tail copy ------------------------------
__global__ void init_state(const float* __restrict__ hidden, const float* __restrict__ cell){
    int i = blockIdx.x * 256 + threadIdx.x;
    g_h[0][i] = hidden[i];
    g_c[i]    = cell[i];
    if (blockIdx.x == 0 && threadIdx.x < Bsz) g_flag[threadIdx.x * 8] = 0;
}
__global__ void write_tail(float* __restrict__ out){
    int i = blockIdx.x * 256 + threadIdx.x;
    out[(size_t)Bsz*Tsz*Hsz + i]              = g_h[0][i];
    out[(size_t)Bsz*Tsz*Hsz + Bsz*Hsz + i]    = g_c[i];
}

// ---------------- launcher ---------------------------------------------------
extern "C" void kernel_launch(void* const* d_in, const int* in_sizes, int n_in,
                              void* d_out, int out_size)
{
    const float *x, *xd, *hidden, *cell;
    const float *Wii,*Wif,*Wig,*Wio,*Wid,*Wro,*Whi,*Whf,*Whg,*Who,*Whd;
    const float *bi,*bf,*bg,*bo,*bd,*Wrb;

    x      = (const float*)d_in[0];
    xd     = (const float*)d_in[1];
    hidden = (const float*)d_in[2];
    cell   = (const float*)d_in[3];

    if (in_sizes[5] == Hsz*Isz) {
        Wii=(const float*)d_in[4];  Wif=(const float*)d_in[5];  Wig=(const float*)d_in[6];
        Wio=(const float*)d_in[7];  Wid=(const float*)d_in[8];  Wro=(const float*)d_in[9];
        Whi=(const float*)d_in[10]; Whf=(const float*)d_in[11]; Whg=(const float*)d_in[12];
        Who=(const float*)d_in[13]; Whd=(const float*)d_in[14];
        bi=(const float*)d_in[15];  bf=(const float*)d_in[16];  bg=(const float*)d_in[17];
        bo=(const float*)d_in[18];  bd=(const float*)d_in[19];  Wrb=(const float*)d_in[20];
    } else {
        Wii=(const float*)d_in[4];  Whi=(const float*)d_in[5];  bi =(const float*)d_in[6];
        Wif=(const float*)d_in[7];  Whf=(const float*)d_in[8];  bf =(const float*)d_in[9];
        Wig=(const float*)d_in[10]; Whg=(const float*)d_in[11]; bg =(const float*)d_in[12];
        Wio=(const float*)d_in[13]; Who=(const float*)d_in[14]; bo =(const float*)d_in[15];
        Wid=(const float*)d_in[16]; Whd=(const float*)d_in[17]; bd =(const float*)d_in[18];
        Wro=(const float*)d_in[19]; Wrb=(const float*)d_in[20];
    }

    float* out = (float*)d_out;

    cudaFuncSetAttribute(lstm_persist, cudaFuncAttributeMaxDynamicSharedMemorySize,
                         SMEM_FLOATS * (int)sizeof(float));

    init_state<<<(Bsz*Hsz)/256, 256>>>(hidden, cell);

    dim3 gpre(Hsz/BN, Mpre/BM, 5);
    gemm_pre<<<gpre, 256>>>(x, xd, Wii, Wif, Wig, Wio, Wid, bi, bf, bg, bo, bd);

    lstm_persist<<<Bsz, 512, SMEM_FLOATS * (int)sizeof(float)>>>(Whi, Whf, Whg, Who, Whd);

    gemm_out<<<dim3(Hsz/BN, Mpre/BM), 256>>>(x, Wro, Who, Wrb, out);

    write_tail<<<(Bsz*Hsz)/256, 256>>>(out);
}